// round 4
// baseline (speedup 1.0000x reference)
#include <cuda_runtime.h>
#include <cstdint>

#define N_ROWS  262144
#define DIM     256
#define CLUSTER 512
#define SLACK   1024
#define NPAIRS  (CLUSTER * (CLUSTER - 1) / 2)   // 130816
#define NTILES  136                             // 16*17/2 upper-tri 32x32 tiles

// ---- device scratch (no allocations allowed) ----
__device__ int   d_cursor[CLUSTER];
__device__ int   d_perm[CLUSTER * SLACK];            // 2 MB
__device__ float d_partial[2][CLUSTER][DIM];         // 1 MB
__device__ float d_centers[CLUSTER * DIM];           // 512 KB (L2-resident)
__device__ float d_norms[CLUSTER];
__device__ float d_pair_sum;

__device__ __forceinline__ void cp16(uint32_t dst, const float* src) {
    asm volatile("cp.async.cg.shared.global [%0], [%1], 16;\n"
                 :: "r"(dst), "l"(src));
}
__device__ __forceinline__ void cp_commit() {
    asm volatile("cp.async.commit_group;\n");
}
__device__ __forceinline__ void cp_wait1() {
    asm volatile("cp.async.wait_group 1;\n");
}
__device__ __forceinline__ void cp_wait0() {
    asm volatile("cp.async.wait_group 0;\n");
}

// ---------------------------------------------------------------------------
// k_init: reset cursors + pair accumulator (graph replays reuse them).
// ---------------------------------------------------------------------------
__global__ void k_init() {
    int t = blockIdx.x * blockDim.x + threadIdx.x;
    if (t < CLUSTER) d_cursor[t] = t * SLACK;
    if (t == 0) d_pair_sum = 0.0f;
}

// ---------------------------------------------------------------------------
// k_scatter: counting scatter of row indices into per-cluster buckets.
// ---------------------------------------------------------------------------
__global__ void __launch_bounds__(512) k_scatter(const int* __restrict__ label) {
    int r = blockIdx.x * blockDim.x + threadIdx.x;
    if (r < N_ROWS) {
        int lab = label[r];
        int pos = atomicAdd(&d_cursor[lab], 1);
        d_perm[pos] = r;
    }
}

// ---------------------------------------------------------------------------
// k_sums: 2 CTAs per cluster (half the rows each), 256 threads.
// cp.async double-buffered 16-row x 1KB stages: full rows fetched
// contiguously, load issue decoupled from consumption, 16KB in flight per
// CTA (~6 CTAs/SM). Consumers read conflict-free float4 columns from smem.
// The 256 MB HBM-bound pass.
// ---------------------------------------------------------------------------
__global__ void __launch_bounds__(256) k_sums(const float* __restrict__ matrix) {
    int bx = blockIdx.x;
    int c  = bx >> 1;
    int h  = bx & 1;
    int t  = threadIdx.x;

    int cnt   = d_cursor[c] - c * SLACK;
    int half  = (cnt + 1) >> 1;
    int start = h * half;
    int m     = min(cnt, start + half) - start;     // rows for this CTA
    const int* __restrict__ p = d_perm + c * SLACK + start;

    __shared__ float  buf[2][16][DIM];              // 32 KB
    __shared__ float4 part[256];                    // 4 KB

    int lr = t >> 4;       // loader row 0..15
    int ch = t & 15;       // loader 64B chunk
    int cg = t & 63;       // consumer float4 column group
    int s  = t >> 6;       // consumer row slot 0..3

    float4 acc = make_float4(0.f, 0.f, 0.f, 0.f);

    if (m > 0) {
        int nst = (m + 15) >> 4;
        // prologue: stage 0
        {
            int row = p[min(lr, m - 1)];
            uint32_t dst = (uint32_t)__cvta_generic_to_shared(&buf[0][lr][ch * 16]);
            const float* src = matrix + (size_t)row * DIM + ch * 16;
#pragma unroll
            for (int k = 0; k < 4; k++) cp16(dst + k * 16, src + k * 4);
            cp_commit();
        }
        for (int st = 0; st < nst; st++) {
            if (st + 1 < nst) {
                int rpos = (st + 1) * 16 + lr;
                int row  = p[min(rpos, m - 1)];
                uint32_t dst = (uint32_t)__cvta_generic_to_shared(
                    &buf[(st + 1) & 1][lr][ch * 16]);
                const float* src = matrix + (size_t)row * DIM + ch * 16;
#pragma unroll
                for (int k = 0; k < 4; k++) cp16(dst + k * 16, src + k * 4);
                cp_commit();
                cp_wait1();
            } else {
                cp_wait0();
            }
            __syncthreads();
            int lim = m - st * 16;                  // up to 16 valid rows
            const float (*B)[DIM] = buf[st & 1];
#pragma unroll
            for (int k = 0; k < 4; k++) {
                int rr = s + k * 4;
                if (rr < lim) {
                    float4 v = *(const float4*)&B[rr][cg * 4];
                    acc.x += v.x; acc.y += v.y; acc.z += v.z; acc.w += v.w;
                }
            }
            __syncthreads();                        // before stage st+2 overwrites
        }
    }

    // reduce the 4 row slots -> partial half-sum
    part[t] = acc;
    __syncthreads();
    if (t < 64) {
        float4 a0 = part[t], a1 = part[t + 64], a2 = part[t + 128], a3 = part[t + 192];
        float4 o;
        o.x = (a0.x + a1.x) + (a2.x + a3.x);
        o.y = (a0.y + a1.y) + (a2.y + a3.y);
        o.z = (a0.z + a1.z) + (a2.z + a3.z);
        o.w = (a0.w + a1.w) + (a2.w + a3.w);
        *(float4*)&d_partial[h][c][t * 4] = o;
    }
}

// ---------------------------------------------------------------------------
// k_norm: combine halves, normalize, emit centers + squared norms.
// ---------------------------------------------------------------------------
__global__ void __launch_bounds__(64) k_norm() {
    int c = blockIdx.x;
    int t = threadIdx.x;
    int cnt = d_cursor[c] - c * SLACK;
    float inv = 1.0f / fmaxf((float)cnt, 1.0f);

    float4 a = *(const float4*)&d_partial[0][c][t * 4];
    float4 b = *(const float4*)&d_partial[1][c][t * 4];
    float4 cen;
    cen.x = (a.x + b.x) * inv;
    cen.y = (a.y + b.y) * inv;
    cen.z = (a.z + b.z) * inv;
    cen.w = (a.w + b.w) * inv;
    *(float4*)&d_centers[c * DIM + t * 4] = cen;

    float nrm = cen.x * cen.x + cen.y * cen.y + cen.z * cen.z + cen.w * cen.w;
#pragma unroll
    for (int o = 16; o > 0; o >>= 1)
        nrm += __shfl_down_sync(0xFFFFFFFFu, nrm, o);
    __shared__ float w2[2];
    if ((t & 31) == 0) w2[t >> 5] = nrm;
    __syncthreads();
    if (t == 0) d_norms[c] = w2[0] + w2[1];
}

// ---------------------------------------------------------------------------
// k_pdist: 136 upper-tri 32x32 tiles, 256 threads.
// Transposed smem tiles At[d][i] (d-major, pad 36): per-d outer product,
// 2 broadcast conflict-free LDS.128 feed 16 FFMA (4x4 micro-tile).
// Split-d x4 across warps; partial dots reduced through smem (stride 17).
// ---------------------------------------------------------------------------
#define TPAD 36
__global__ void __launch_bounds__(256) k_pdist() {
    // decode upper-tri tile index -> (bi, bj), bi <= bj
    int n = blockIdx.x;
    int bi = 0;
    while (n >= 16 - bi) { n -= 16 - bi; bi++; }
    int bj = bi + n;

    __shared__ float At[128][TPAD];   // 18432 B, reused as reduction scratch
    __shared__ float Bt[128][TPAD];

    int t  = threadIdx.x;
    int tt = t & 63;       // 4x4 micro-tile position
    int ds = t >> 6;       // d-slice 0..3 (uniform per warp)
    int ti = tt >> 3;      // i block 0..7  -> rows ti*4..ti*4+3
    int tj = tt & 7;       // j block 0..7  -> rows tj*4..tj*4+3

    float acc[4][4];
#pragma unroll
    for (int a = 0; a < 4; a++)
#pragma unroll
        for (int b = 0; b < 4; b++) acc[a][b] = 0.0f;

    for (int ck = 0; ck < DIM; ck += 128) {
        __syncthreads();
        // transpose-load: thread -> row i = t>>3, d-chunks dc = t&7 (+8 step)
        int i = t >> 3;
        for (int dc = t & 7; dc < 32; dc += 8) {
            float4 va = *(const float4*)&d_centers[(bi * 32 + i) * DIM + ck + dc * 4];
            float4 vb = *(const float4*)&d_centers[(bj * 32 + i) * DIM + ck + dc * 4];
            At[dc * 4 + 0][i] = va.x; At[dc * 4 + 1][i] = va.y;
            At[dc * 4 + 2][i] = va.z; At[dc * 4 + 3][i] = va.w;
            Bt[dc * 4 + 0][i] = vb.x; Bt[dc * 4 + 1][i] = vb.y;
            Bt[dc * 4 + 2][i] = vb.z; Bt[dc * 4 + 3][i] = vb.w;
        }
        __syncthreads();

#pragma unroll 8
        for (int d = ds * 32; d < ds * 32 + 32; d++) {
            float4 aV = *(const float4*)&At[d][ti * 4];
            float4 bV = *(const float4*)&Bt[d][tj * 4];
            acc[0][0] += aV.x * bV.x; acc[0][1] += aV.x * bV.y;
            acc[0][2] += aV.x * bV.z; acc[0][3] += aV.x * bV.w;
            acc[1][0] += aV.y * bV.x; acc[1][1] += aV.y * bV.y;
            acc[1][2] += aV.y * bV.z; acc[1][3] += aV.y * bV.w;
            acc[2][0] += aV.z * bV.x; acc[2][1] += aV.z * bV.y;
            acc[2][2] += aV.z * bV.z; acc[2][3] += aV.z * bV.w;
            acc[3][0] += aV.w * bV.x; acc[3][1] += aV.w * bV.y;
            acc[3][2] += aV.w * bV.z; acc[3][3] += aV.w * bV.w;
        }
    }

    __syncthreads();
    float* red = &At[0][0];   // needs 4*64*17 = 4352 floats; At holds 4608
#pragma unroll
    for (int a = 0; a < 4; a++)
#pragma unroll
        for (int b = 0; b < 4; b++)
            red[(ds * 64 + tt) * 17 + a * 4 + b] = acc[a][b];
    __syncthreads();

    float local = 0.0f;
#pragma unroll
    for (int q = 0; q < 4; q++) {
        int pp  = t * 4 + q;          // pair 0..1023
        int tt2 = pp >> 4;
        int e   = pp & 15;
        float dot = red[tt2 * 17 + e] + red[(64 + tt2) * 17 + e] +
                    red[(128 + tt2) * 17 + e] + red[(192 + tt2) * 17 + e];
        int i2 = (tt2 >> 3) * 4 + (e >> 2);
        int j2 = (tt2 & 7) * 4 + (e & 3);
        int gi = bi * 32 + i2;
        int gj = bj * 32 + j2;
        if (gi < gj) {
            float sq = d_norms[gi] + d_norms[gj] - 2.0f * dot;
            local += sqrtf(fmaxf(sq, 1e-12f));
        }
    }

    // block reduce -> one atomicAdd
#pragma unroll
    for (int o = 16; o > 0; o >>= 1)
        local += __shfl_down_sync(0xFFFFFFFFu, local, o);
    __shared__ float partw[8];
    if ((t & 31) == 0) partw[t >> 5] = local;
    __syncthreads();
    if (t == 0) {
        float sum = 0.0f;
#pragma unroll
        for (int i = 0; i < 8; i++) sum += partw[i];
        atomicAdd(&d_pair_sum, sum);
    }
}

// ---------------------------------------------------------------------------
__global__ void k_final(float* __restrict__ out) {
    out[0] = -d_pair_sum / (float)NPAIRS;
}

// ---------------------------------------------------------------------------
extern "C" void kernel_launch(void* const* d_in, const int* in_sizes, int n_in,
                              void* d_out, int out_size) {
    const float* matrix = (const float*)d_in[0];
    const int*   label  = (const int*)d_in[1];
    float*       out    = (float*)d_out;

    k_init<<<1, 512>>>();
    k_scatter<<<N_ROWS / 512, 512>>>(label);
    k_sums<<<CLUSTER * 2, 256>>>(matrix);
    k_norm<<<CLUSTER, 64>>>();
    k_pdist<<<NTILES, 256>>>();
    k_final<<<1, 1>>>(out);
}

// round 5
// speedup vs baseline: 1.7110x; 1.7110x over previous
#include <cuda_runtime.h>
#include <cstdint>

#define N_ROWS  262144
#define DIM     256
#define CLUSTER 512
#define SLACK   1024
#define NPAIRS  (CLUSTER * (CLUSTER - 1) / 2)   // 130816
#define NTILES  136                             // 16*17/2 upper-tri 32x32 tiles
#define SCTAS   128
#define ROWS_PER_SCTA (N_ROWS / SCTAS)          // 2048

// ---- device scratch (no allocations allowed) ----
__device__ int   d_cursor[CLUSTER];
__device__ int   d_perm[CLUSTER * SLACK];          // 2 MB
__device__ float d_centers[CLUSTER * DIM];         // 512 KB (L2-resident)
__device__ float d_norms[CLUSTER];
__device__ float d_pair_sum;

__device__ __forceinline__ float4 ldcs4(const float* p) {
    float4 v;
    asm volatile("ld.global.cs.v4.f32 {%0,%1,%2,%3}, [%4];"
                 : "=f"(v.x), "=f"(v.y), "=f"(v.z), "=f"(v.w) : "l"(p));
    return v;
}

// ---------------------------------------------------------------------------
// k_init: reset cursors, norms, pair accumulator (graph replays reuse them).
// ---------------------------------------------------------------------------
__global__ void k_init() {
    int t = blockIdx.x * blockDim.x + threadIdx.x;
    if (t < CLUSTER) {
        d_cursor[t] = t * SLACK;
        d_norms[t]  = 0.0f;
    }
    if (t == 0) d_pair_sum = 0.0f;
}

// ---------------------------------------------------------------------------
// k_scatter: CTA-aggregated counting scatter. Two passes over 2048 rows:
// smem histogram -> ONE global atomicAdd per (CTA, cluster) to reserve a
// range (warp-wide ops hit 32 DISTINCT consecutive addresses -> no hot-line
// serialization) -> smem cursors -> write positions.
// ---------------------------------------------------------------------------
__global__ void __launch_bounds__(512) k_scatter(const int* __restrict__ label) {
    __shared__ int hist[CLUSTER];
    __shared__ int curs[CLUSTER];
    int t  = threadIdx.x;
    int r0 = blockIdx.x * ROWS_PER_SCTA;

    hist[t] = 0;
    __syncthreads();

    int labs[4];
#pragma unroll
    for (int k = 0; k < 4; k++) {
        labs[k] = label[r0 + k * 512 + t];
        atomicAdd(&hist[labs[k]], 1);
    }
    __syncthreads();

    int h = hist[t];
    curs[t] = (h > 0) ? atomicAdd(&d_cursor[t], h) : 0;
    __syncthreads();

#pragma unroll
    for (int k = 0; k < 4; k++) {
        int pos = atomicAdd(&curs[labs[k]], 1);
        d_perm[pos] = r0 + k * 512 + t;
    }
}

// ---------------------------------------------------------------------------
// k_sums: 4 CTAs per cluster (64-column quarters), 128 threads =
// 16 column-groups (float4) x 8 row-slots. Each thread keeps 8 independent
// LDG.128 in flight (explicit v[8] batch + add tree). Streaming (.cs) loads:
// matrix has zero reuse. The 256 MB HBM-bound pass.
// ---------------------------------------------------------------------------
__global__ void __launch_bounds__(128) k_sums(const float* __restrict__ matrix) {
    int bx   = blockIdx.x;
    int c    = bx >> 2;
    int quad = bx & 3;
    int t    = threadIdx.x;
    int cg   = t & 15;
    int s    = t >> 4;
    int colbase = quad * 64 + cg * 4;

    int cnt = d_cursor[c] - c * SLACK;
    const int* __restrict__ p = d_perm + c * SLACK;

    __shared__ int    sidx[256];
    __shared__ float4 part[128];

    float4 acc = make_float4(0.f, 0.f, 0.f, 0.f);

    int base = 0;
    for (; base + 256 <= cnt; base += 256) {
        __syncthreads();
        sidx[t]       = p[base + t];
        sidx[t + 128] = p[base + t + 128];
        __syncthreads();
        for (int r = 0; r < 32; r += 8) {
            float4 v[8];
#pragma unroll
            for (int u = 0; u < 8; u++) {
                int row = sidx[(r + u) * 8 + s];
                v[u] = ldcs4(&matrix[(size_t)row * DIM + colbase]);
            }
            float4 s01, s23, s45, s67, sA, sB;
            s01.x = v[0].x + v[1].x; s01.y = v[0].y + v[1].y; s01.z = v[0].z + v[1].z; s01.w = v[0].w + v[1].w;
            s23.x = v[2].x + v[3].x; s23.y = v[2].y + v[3].y; s23.z = v[2].z + v[3].z; s23.w = v[2].w + v[3].w;
            s45.x = v[4].x + v[5].x; s45.y = v[4].y + v[5].y; s45.z = v[4].z + v[5].z; s45.w = v[4].w + v[5].w;
            s67.x = v[6].x + v[7].x; s67.y = v[6].y + v[7].y; s67.z = v[6].z + v[7].z; s67.w = v[6].w + v[7].w;
            sA.x = s01.x + s23.x; sA.y = s01.y + s23.y; sA.z = s01.z + s23.z; sA.w = s01.w + s23.w;
            sB.x = s45.x + s67.x; sB.y = s45.y + s67.y; sB.z = s45.z + s67.z; sB.w = s45.w + s67.w;
            acc.x += sA.x + sB.x; acc.y += sA.y + sB.y;
            acc.z += sA.z + sB.z; acc.w += sA.w + sB.w;
        }
    }
    {   // tail
        int m = cnt - base;
        __syncthreads();
        if (t < m)       sidx[t]       = p[base + t];
        if (t + 128 < m) sidx[t + 128] = p[base + t + 128];
        __syncthreads();
        for (int r = s; r < m; r += 8) {
            int row = sidx[r];
            float4 v = ldcs4(&matrix[(size_t)row * DIM + colbase]);
            acc.x += v.x; acc.y += v.y; acc.z += v.z; acc.w += v.w;
        }
    }

    part[t] = acc;
    __syncthreads();

    if (t < 16) {
        float4 cen = make_float4(0.f, 0.f, 0.f, 0.f);
#pragma unroll
        for (int k = 0; k < 8; k++) {
            float4 a = part[t + k * 16];
            cen.x += a.x; cen.y += a.y; cen.z += a.z; cen.w += a.w;
        }
        float inv = 1.0f / fmaxf((float)cnt, 1.0f);
        cen.x *= inv; cen.y *= inv; cen.z *= inv; cen.w *= inv;
        *(float4*)&d_centers[c * DIM + quad * 64 + t * 4] = cen;

        float nrm = cen.x * cen.x + cen.y * cen.y + cen.z * cen.z + cen.w * cen.w;
#pragma unroll
        for (int o = 8; o > 0; o >>= 1)
            nrm += __shfl_down_sync(0xFFFFu, nrm, o);
        if (t == 0) atomicAdd(&d_norms[c], nrm);
    }
}

// ---------------------------------------------------------------------------
// k_pdist: 136 upper-tri 32x32 tiles, 256 threads.
// Transposed smem tiles At[d][i] (d-major, pad 36): per-d outer product,
// 2 broadcast conflict-free LDS.128 feed 16 FFMA (4x4 micro-tile).
// Split-d x4 across warps; partial dots reduced through smem (stride 17).
// ---------------------------------------------------------------------------
#define TPAD 36
__global__ void __launch_bounds__(256) k_pdist() {
    int n = blockIdx.x;
    int bi = 0;
    while (n >= 16 - bi) { n -= 16 - bi; bi++; }
    int bj = bi + n;

    __shared__ float At[128][TPAD];   // reused as reduction scratch
    __shared__ float Bt[128][TPAD];

    int t  = threadIdx.x;
    int tt = t & 63;
    int ds = t >> 6;
    int ti = tt >> 3;
    int tj = tt & 7;

    float acc[4][4];
#pragma unroll
    for (int a = 0; a < 4; a++)
#pragma unroll
        for (int b = 0; b < 4; b++) acc[a][b] = 0.0f;

    for (int ck = 0; ck < DIM; ck += 128) {
        __syncthreads();
        int i = t >> 3;
        for (int dc = t & 7; dc < 32; dc += 8) {
            float4 va = *(const float4*)&d_centers[(bi * 32 + i) * DIM + ck + dc * 4];
            float4 vb = *(const float4*)&d_centers[(bj * 32 + i) * DIM + ck + dc * 4];
            At[dc * 4 + 0][i] = va.x; At[dc * 4 + 1][i] = va.y;
            At[dc * 4 + 2][i] = va.z; At[dc * 4 + 3][i] = va.w;
            Bt[dc * 4 + 0][i] = vb.x; Bt[dc * 4 + 1][i] = vb.y;
            Bt[dc * 4 + 2][i] = vb.z; Bt[dc * 4 + 3][i] = vb.w;
        }
        __syncthreads();

#pragma unroll 8
        for (int d = ds * 32; d < ds * 32 + 32; d++) {
            float4 aV = *(const float4*)&At[d][ti * 4];
            float4 bV = *(const float4*)&Bt[d][tj * 4];
            acc[0][0] += aV.x * bV.x; acc[0][1] += aV.x * bV.y;
            acc[0][2] += aV.x * bV.z; acc[0][3] += aV.x * bV.w;
            acc[1][0] += aV.y * bV.x; acc[1][1] += aV.y * bV.y;
            acc[1][2] += aV.y * bV.z; acc[1][3] += aV.y * bV.w;
            acc[2][0] += aV.z * bV.x; acc[2][1] += aV.z * bV.y;
            acc[2][2] += aV.z * bV.z; acc[2][3] += aV.z * bV.w;
            acc[3][0] += aV.w * bV.x; acc[3][1] += aV.w * bV.y;
            acc[3][2] += aV.w * bV.z; acc[3][3] += aV.w * bV.w;
        }
    }

    __syncthreads();
    float* red = &At[0][0];   // 4*64*17 = 4352 floats; At holds 4608
#pragma unroll
    for (int a = 0; a < 4; a++)
#pragma unroll
        for (int b = 0; b < 4; b++)
            red[(ds * 64 + tt) * 17 + a * 4 + b] = acc[a][b];
    __syncthreads();

    float local = 0.0f;
#pragma unroll
    for (int q = 0; q < 4; q++) {
        int pp  = t * 4 + q;
        int tt2 = pp >> 4;
        int e   = pp & 15;
        float dot = red[tt2 * 17 + e] + red[(64 + tt2) * 17 + e] +
                    red[(128 + tt2) * 17 + e] + red[(192 + tt2) * 17 + e];
        int i2 = (tt2 >> 3) * 4 + (e >> 2);
        int j2 = (tt2 & 7) * 4 + (e & 3);
        int gi = bi * 32 + i2;
        int gj = bj * 32 + j2;
        if (gi < gj) {
            float sq = d_norms[gi] + d_norms[gj] - 2.0f * dot;
            local += sqrtf(fmaxf(sq, 1e-12f));
        }
    }

#pragma unroll
    for (int o = 16; o > 0; o >>= 1)
        local += __shfl_down_sync(0xFFFFFFFFu, local, o);
    __shared__ float partw[8];
    if ((t & 31) == 0) partw[t >> 5] = local;
    __syncthreads();
    if (t == 0) {
        float sum = 0.0f;
#pragma unroll
        for (int i = 0; i < 8; i++) sum += partw[i];
        atomicAdd(&d_pair_sum, sum);
    }
}

// ---------------------------------------------------------------------------
__global__ void k_final(float* __restrict__ out) {
    out[0] = -d_pair_sum / (float)NPAIRS;
}

// ---------------------------------------------------------------------------
extern "C" void kernel_launch(void* const* d_in, const int* in_sizes, int n_in,
                              void* d_out, int out_size) {
    const float* matrix = (const float*)d_in[0];
    const int*   label  = (const int*)d_in[1];
    float*       out    = (float*)d_out;

    k_init<<<1, 512>>>();
    k_scatter<<<SCTAS, 512>>>(label);
    k_sums<<<CLUSTER * 4, 128>>>(matrix);
    k_pdist<<<NTILES, 256>>>();
    k_final<<<1, 1>>>(out);
}

// round 6
// speedup vs baseline: 1.8215x; 1.0646x over previous
#include <cuda_runtime.h>
#include <cstdint>

#define N_ROWS  262144
#define DIM     256
#define CLUSTER 512
#define SLACK   1024
#define NPAIRS  (CLUSTER * (CLUSTER - 1) / 2)   // 130816
#define NTILES  136                             // 16*17/2 upper-tri 32x32 tiles
#define SCTAS   128
#define ROWS_PER_SCTA (N_ROWS / SCTAS)          // 2048

// ---- device scratch (no allocations allowed) ----
__device__ int   d_cursor[CLUSTER];
__device__ int   d_perm[CLUSTER * SLACK];          // 2 MB
__device__ float d_centers[CLUSTER * DIM];         // 512 KB (L2-resident)
__device__ float d_norms[CLUSTER];
__device__ float d_pair_sum;

__device__ __forceinline__ float4 ldcs4(const float* p) {
    float4 v;
    asm volatile("ld.global.cs.v4.f32 {%0,%1,%2,%3}, [%4];"
                 : "=f"(v.x), "=f"(v.y), "=f"(v.z), "=f"(v.w) : "l"(p));
    return v;
}

// ---------------------------------------------------------------------------
// k_init
// ---------------------------------------------------------------------------
__global__ void k_init() {
    int t = blockIdx.x * blockDim.x + threadIdx.x;
    if (t < CLUSTER) {
        d_cursor[t] = t * SLACK;
        d_norms[t]  = 0.0f;
    }
    if (t == 0) d_pair_sum = 0.0f;
}

// ---------------------------------------------------------------------------
// k_scatter: CTA-aggregated counting scatter (one global atomic per
// (CTA, cluster), distinct consecutive addresses -> no hot-line serialization).
// ---------------------------------------------------------------------------
__global__ void __launch_bounds__(512) k_scatter(const int* __restrict__ label) {
    __shared__ int hist[CLUSTER];
    __shared__ int curs[CLUSTER];
    int t  = threadIdx.x;
    int r0 = blockIdx.x * ROWS_PER_SCTA;

    hist[t] = 0;
    __syncthreads();

    int labs[4];
#pragma unroll
    for (int k = 0; k < 4; k++) {
        labs[k] = label[r0 + k * 512 + t];
        atomicAdd(&hist[labs[k]], 1);
    }
    __syncthreads();

    int h = hist[t];
    curs[t] = (h > 0) ? atomicAdd(&d_cursor[t], h) : 0;
    __syncthreads();

#pragma unroll
    for (int k = 0; k < 4; k++) {
        int pos = atomicAdd(&curs[labs[k]], 1);
        d_perm[pos] = r0 + k * 512 + t;
    }
}

// ---------------------------------------------------------------------------
// k_sums: 2 CTAs per cluster (128-column halves), 256 threads =
// 32 column-groups (float4) x 8 row-slots. Each thread keeps 8 independent
// LDG.128 in flight; each warp request covers 512B contiguous of one row
// (half the DRAM row-activations vs quarter-split). The 256 MB HBM pass.
// ---------------------------------------------------------------------------
__global__ void __launch_bounds__(256) k_sums(const float* __restrict__ matrix) {
    int bx = blockIdx.x;
    int c  = bx >> 1;
    int hc = bx & 1;
    int t  = threadIdx.x;
    int cg = t & 31;           // float4 group within the half
    int s  = t >> 5;           // row slot 0..7
    int colbase = hc * 128 + cg * 4;

    int cnt = d_cursor[c] - c * SLACK;
    const int* __restrict__ p = d_perm + c * SLACK;

    __shared__ int    sidx[256];
    __shared__ float4 part[256];

    float4 acc = make_float4(0.f, 0.f, 0.f, 0.f);

    int base = 0;
    for (; base + 256 <= cnt; base += 256) {
        __syncthreads();
        sidx[t] = p[base + t];
        __syncthreads();
        for (int r = 0; r < 32; r += 8) {
            float4 v[8];
#pragma unroll
            for (int u = 0; u < 8; u++) {
                int row = sidx[(r + u) * 8 + s];
                v[u] = ldcs4(&matrix[(size_t)row * DIM + colbase]);
            }
            float4 s01, s23, s45, s67, sA, sB;
            s01.x = v[0].x + v[1].x; s01.y = v[0].y + v[1].y; s01.z = v[0].z + v[1].z; s01.w = v[0].w + v[1].w;
            s23.x = v[2].x + v[3].x; s23.y = v[2].y + v[3].y; s23.z = v[2].z + v[3].z; s23.w = v[2].w + v[3].w;
            s45.x = v[4].x + v[5].x; s45.y = v[4].y + v[5].y; s45.z = v[4].z + v[5].z; s45.w = v[4].w + v[5].w;
            s67.x = v[6].x + v[7].x; s67.y = v[6].y + v[7].y; s67.z = v[6].z + v[7].z; s67.w = v[6].w + v[7].w;
            sA.x = s01.x + s23.x; sA.y = s01.y + s23.y; sA.z = s01.z + s23.z; sA.w = s01.w + s23.w;
            sB.x = s45.x + s67.x; sB.y = s45.y + s67.y; sB.z = s45.z + s67.z; sB.w = s45.w + s67.w;
            acc.x += sA.x + sB.x; acc.y += sA.y + sB.y;
            acc.z += sA.z + sB.z; acc.w += sA.w + sB.w;
        }
    }
    {   // tail
        int m = cnt - base;
        __syncthreads();
        if (t < m) sidx[t] = p[base + t];
        __syncthreads();
        for (int r = s; r < m; r += 8) {
            int row = sidx[r];
            float4 v = ldcs4(&matrix[(size_t)row * DIM + colbase]);
            acc.x += v.x; acc.y += v.y; acc.z += v.z; acc.w += v.w;
        }
    }

    part[t] = acc;
    __syncthreads();

    if (t < 32) {
        float4 cen = make_float4(0.f, 0.f, 0.f, 0.f);
#pragma unroll
        for (int k = 0; k < 8; k++) {
            float4 a = part[t + k * 32];
            cen.x += a.x; cen.y += a.y; cen.z += a.z; cen.w += a.w;
        }
        float inv = 1.0f / fmaxf((float)cnt, 1.0f);
        cen.x *= inv; cen.y *= inv; cen.z *= inv; cen.w *= inv;
        *(float4*)&d_centers[c * DIM + hc * 128 + t * 4] = cen;

        float nrm = cen.x * cen.x + cen.y * cen.y + cen.z * cen.z + cen.w * cen.w;
#pragma unroll
        for (int o = 16; o > 0; o >>= 1)
            nrm += __shfl_down_sync(0xFFFFFFFFu, nrm, o);
        if (t == 0) atomicAdd(&d_norms[c], nrm);
    }
}

// ---------------------------------------------------------------------------
// k_pdist: 136 upper-tri 32x32 tiles, 512 threads (16 warps).
// Transposed smem tiles T[d][i] (TPAD=36): loader gathers 4 i-values per
// (d, iblock) via coalesced LDG.32 columns and stores ONE STS.128 -> 16B
// units land on bank-groups (d+iblk) mod 8: conflict-free store phases.
// Compute: 8 d-slices x 64 threads; per d, 2 broadcast LDS.128 feed 16 FFMA
// (4x4 micro-tile). Partial dots reduced through smem (stride 17).
// ---------------------------------------------------------------------------
#define TPAD 36
__global__ void __launch_bounds__(512) k_pdist() {
    // decode upper-tri tile index -> (bi, bj), bi <= bj
    int n = blockIdx.x;
    int bi = 0;
    while (n >= 16 - bi) { n -= 16 - bi; bi++; }
    int bj = bi + n;

    __shared__ __align__(16) float S[2 * 128 * TPAD];   // 36864 B
    float (*At)[TPAD] = (float (*)[TPAD])S;
    float (*Bt)[TPAD] = (float (*)[TPAD])(S + 128 * TPAD);

    int t    = threadIdx.x;
    int tt   = t & 63;         // micro-tile position
    int ds   = t >> 6;         // d-slice 0..7
    int ti   = tt >> 3;        // i block 0..7
    int tj   = tt & 7;         // j block 0..7

    // loader mapping
    int half = t >> 8;         // 0 -> A, 1 -> B
    int iblk = (t >> 5) & 7;   // i block 0..7
    int dlo  = t & 31;         // d lane

    float acc[4][4];
#pragma unroll
    for (int a = 0; a < 4; a++)
#pragma unroll
        for (int b = 0; b < 4; b++) acc[a][b] = 0.0f;

    for (int ck = 0; ck < DIM; ck += 128) {
        __syncthreads();
        {
            int bX = half ? bj : bi;
            float (*T)[TPAD] = half ? Bt : At;
            const float* src = &d_centers[(bX * 32 + iblk * 4) * DIM + ck];
#pragma unroll
            for (int k = 0; k < 4; k++) {
                int dd = dlo + k * 32;
                float4 v;
                v.x = src[0 * DIM + dd];
                v.y = src[1 * DIM + dd];
                v.z = src[2 * DIM + dd];
                v.w = src[3 * DIM + dd];
                *(float4*)&T[dd][iblk * 4] = v;
            }
        }
        __syncthreads();

#pragma unroll 8
        for (int d = ds * 16 + (ck >> 3); d < ds * 16 + (ck >> 3) + 16; d++) {
            float4 aV = *(float4*)&At[d - (ck >> 3) + 0][ti * 4];
            float4 bV = *(float4*)&Bt[d - (ck >> 3) + 0][tj * 4];
            acc[0][0] += aV.x * bV.x; acc[0][1] += aV.x * bV.y;
            acc[0][2] += aV.x * bV.z; acc[0][3] += aV.x * bV.w;
            acc[1][0] += aV.y * bV.x; acc[1][1] += aV.y * bV.y;
            acc[1][2] += aV.y * bV.z; acc[1][3] += aV.y * bV.w;
            acc[2][0] += aV.z * bV.x; acc[2][1] += aV.z * bV.y;
            acc[2][2] += aV.z * bV.z; acc[2][3] += aV.z * bV.w;
            acc[3][0] += aV.w * bV.x; acc[3][1] += aV.w * bV.y;
            acc[3][2] += aV.w * bV.z; acc[3][3] += aV.w * bV.w;
        }
    }

    // slice-partial reduction through smem: red[(ds*64+tt)*17 + e]
    __syncthreads();
    float* red = S;            // needs 512*17 = 8704 floats <= 9216
#pragma unroll
    for (int a = 0; a < 4; a++)
#pragma unroll
        for (int b = 0; b < 4; b++)
            red[(ds * 64 + tt) * 17 + a * 4 + b] = acc[a][b];
    __syncthreads();

    float local = 0.0f;
#pragma unroll
    for (int q = 0; q < 2; q++) {
        int pp  = t * 2 + q;          // pair 0..1023
        int tt2 = pp >> 4;
        int e   = pp & 15;
        float dot = 0.0f;
#pragma unroll
        for (int sl = 0; sl < 8; sl++)
            dot += red[(sl * 64 + tt2) * 17 + e];
        int i2 = (tt2 >> 3) * 4 + (e >> 2);
        int j2 = (tt2 & 7) * 4 + (e & 3);
        int gi = bi * 32 + i2;
        int gj = bj * 32 + j2;
        if (gi < gj) {
            float sq = d_norms[gi] + d_norms[gj] - 2.0f * dot;
            local += sqrtf(fmaxf(sq, 1e-12f));
        }
    }

#pragma unroll
    for (int o = 16; o > 0; o >>= 1)
        local += __shfl_down_sync(0xFFFFFFFFu, local, o);
    __shared__ float partw[16];
    if ((t & 31) == 0) partw[t >> 5] = local;
    __syncthreads();
    if (t == 0) {
        float sum = 0.0f;
#pragma unroll
        for (int i = 0; i < 16; i++) sum += partw[i];
        atomicAdd(&d_pair_sum, sum);
    }
}

// ---------------------------------------------------------------------------
__global__ void k_final(float* __restrict__ out) {
    out[0] = -d_pair_sum / (float)NPAIRS;
}

// ---------------------------------------------------------------------------
extern "C" void kernel_launch(void* const* d_in, const int* in_sizes, int n_in,
                              void* d_out, int out_size) {
    const float* matrix = (const float*)d_in[0];
    const int*   label  = (const int*)d_in[1];
    float*       out    = (float*)d_out;

    k_init<<<1, 512>>>();
    k_scatter<<<SCTAS, 512>>>(label);
    k_sums<<<CLUSTER * 2, 256>>>(matrix);
    k_pdist<<<NTILES, 512>>>();
    k_final<<<1, 1>>>(out);
}

// round 7
// speedup vs baseline: 1.8445x; 1.0126x over previous
#include <cuda_runtime.h>
#include <cstdint>

#define N_ROWS  262144
#define DIM     256
#define CLUSTER 512
#define SLACK   1024
#define NPAIRS  (CLUSTER * (CLUSTER - 1) / 2)   // 130816
#define NTILES  136                             // 16*17/2 upper-tri 32x32 tiles
#define SCTAS   128
#define ROWS_PER_SCTA (N_ROWS / SCTAS)          // 2048

// ---- device scratch (no allocations allowed) ----
__device__ int   d_cursor[CLUSTER];
__device__ int   d_perm[CLUSTER * SLACK];          // 2 MB
__device__ float d_centers[CLUSTER * DIM];         // 512 KB (L2-resident)
__device__ float d_norms[CLUSTER];
__device__ float d_pair_sum;
__device__ int   d_done;

__device__ __forceinline__ float4 ldcs4(const float* p) {
    float4 v;
    asm volatile("ld.global.cs.v4.f32 {%0,%1,%2,%3}, [%4];"
                 : "=f"(v.x), "=f"(v.y), "=f"(v.z), "=f"(v.w) : "l"(p));
    return v;
}

// ---------------------------------------------------------------------------
// k_init
// ---------------------------------------------------------------------------
__global__ void k_init() {
    int t = blockIdx.x * blockDim.x + threadIdx.x;
    if (t < CLUSTER) {
        d_cursor[t] = t * SLACK;
        d_norms[t]  = 0.0f;
    }
    if (t == 0) { d_pair_sum = 0.0f; d_done = 0; }
}

// ---------------------------------------------------------------------------
// k_scatter: CTA-aggregated counting scatter (one global atomic per
// (CTA, cluster), distinct consecutive addresses -> no hot-line serialization).
// ---------------------------------------------------------------------------
__global__ void __launch_bounds__(512) k_scatter(const int* __restrict__ label) {
    __shared__ int hist[CLUSTER];
    __shared__ int curs[CLUSTER];
    int t  = threadIdx.x;
    int r0 = blockIdx.x * ROWS_PER_SCTA;

    hist[t] = 0;
    __syncthreads();

    int labs[4];
#pragma unroll
    for (int k = 0; k < 4; k++) {
        labs[k] = label[r0 + k * 512 + t];
        atomicAdd(&hist[labs[k]], 1);
    }
    __syncthreads();

    int h = hist[t];
    curs[t] = (h > 0) ? atomicAdd(&d_cursor[t], h) : 0;
    __syncthreads();

#pragma unroll
    for (int k = 0; k < 4; k++) {
        int pos = atomicAdd(&curs[labs[k]], 1);
        d_perm[pos] = r0 + k * 512 + t;
    }
}

// ---------------------------------------------------------------------------
// k_sums: 2 CTAs per cluster (128-column halves), 256 threads =
// 32 column-groups (float4) x 8 row-slots. Each thread keeps 8 independent
// LDG.128 in flight. Measured at ~6.7 TB/s: HBM roofline-bound. DO NOT TOUCH.
// ---------------------------------------------------------------------------
__global__ void __launch_bounds__(256) k_sums(const float* __restrict__ matrix) {
    int bx = blockIdx.x;
    int c  = bx >> 1;
    int hc = bx & 1;
    int t  = threadIdx.x;
    int cg = t & 31;
    int s  = t >> 5;
    int colbase = hc * 128 + cg * 4;

    int cnt = d_cursor[c] - c * SLACK;
    const int* __restrict__ p = d_perm + c * SLACK;

    __shared__ int    sidx[256];
    __shared__ float4 part[256];

    float4 acc = make_float4(0.f, 0.f, 0.f, 0.f);

    int base = 0;
    for (; base + 256 <= cnt; base += 256) {
        __syncthreads();
        sidx[t] = p[base + t];
        __syncthreads();
        for (int r = 0; r < 32; r += 8) {
            float4 v[8];
#pragma unroll
            for (int u = 0; u < 8; u++) {
                int row = sidx[(r + u) * 8 + s];
                v[u] = ldcs4(&matrix[(size_t)row * DIM + colbase]);
            }
            float4 s01, s23, s45, s67, sA, sB;
            s01.x = v[0].x + v[1].x; s01.y = v[0].y + v[1].y; s01.z = v[0].z + v[1].z; s01.w = v[0].w + v[1].w;
            s23.x = v[2].x + v[3].x; s23.y = v[2].y + v[3].y; s23.z = v[2].z + v[3].z; s23.w = v[2].w + v[3].w;
            s45.x = v[4].x + v[5].x; s45.y = v[4].y + v[5].y; s45.z = v[4].z + v[5].z; s45.w = v[4].w + v[5].w;
            s67.x = v[6].x + v[7].x; s67.y = v[6].y + v[7].y; s67.z = v[6].z + v[7].z; s67.w = v[6].w + v[7].w;
            sA.x = s01.x + s23.x; sA.y = s01.y + s23.y; sA.z = s01.z + s23.z; sA.w = s01.w + s23.w;
            sB.x = s45.x + s67.x; sB.y = s45.y + s67.y; sB.z = s45.z + s67.z; sB.w = s45.w + s67.w;
            acc.x += sA.x + sB.x; acc.y += sA.y + sB.y;
            acc.z += sA.z + sB.z; acc.w += sA.w + sB.w;
        }
    }
    {   // tail
        int m = cnt - base;
        __syncthreads();
        if (t < m) sidx[t] = p[base + t];
        __syncthreads();
        for (int r = s; r < m; r += 8) {
            int row = sidx[r];
            float4 v = ldcs4(&matrix[(size_t)row * DIM + colbase]);
            acc.x += v.x; acc.y += v.y; acc.z += v.z; acc.w += v.w;
        }
    }

    part[t] = acc;
    __syncthreads();

    if (t < 32) {
        float4 cen = make_float4(0.f, 0.f, 0.f, 0.f);
#pragma unroll
        for (int k = 0; k < 8; k++) {
            float4 a = part[t + k * 32];
            cen.x += a.x; cen.y += a.y; cen.z += a.z; cen.w += a.w;
        }
        float inv = 1.0f / fmaxf((float)cnt, 1.0f);
        cen.x *= inv; cen.y *= inv; cen.z *= inv; cen.w *= inv;
        *(float4*)&d_centers[c * DIM + hc * 128 + t * 4] = cen;

        float nrm = cen.x * cen.x + cen.y * cen.y + cen.z * cen.z + cen.w * cen.w;
#pragma unroll
        for (int o = 16; o > 0; o >>= 1)
            nrm += __shfl_down_sync(0xFFFFFFFFu, nrm, o);
        if (t == 0) atomicAdd(&d_norms[c], nrm);
    }
}

// ---------------------------------------------------------------------------
// k_pdist: 136 upper-tri 32x32 tiles, 1024 threads (32 warps, occ 50%).
// Transposed smem tiles T[d][i] (TPAD=36); 16 d-slices x 64 positions;
// per d: 2 broadcast conflict-free LDS.128 feed 16 FFMA (4x4 micro-tile).
// Two-wave slice reduction through smem (stride 17). Last CTA writes output.
// ---------------------------------------------------------------------------
#define TPAD 36
__global__ void __launch_bounds__(1024) k_pdist(float* __restrict__ out) {
    // decode upper-tri tile index -> (bi, bj), bi <= bj
    int n = blockIdx.x;
    int bi = 0;
    while (n >= 16 - bi) { n -= 16 - bi; bi++; }
    int bj = bi + n;

    __shared__ __align__(16) float S[2 * 128 * TPAD];   // 36864 B
    float (*At)[TPAD] = (float (*)[TPAD])S;
    float (*Bt)[TPAD] = (float (*)[TPAD])(S + 128 * TPAD);
    __shared__ float partw[32];

    int t  = threadIdx.x;
    int tt = t & 63;          // micro-tile position
    int ds = t >> 6;          // d-slice 0..15
    int ti = tt >> 3;         // i block 0..7
    int tj = tt & 7;          // j block 0..7

    // loader mapping: 1024 threads, one chunk of 128 dims per phase
    int half = t >> 9;        // 0 -> A, 1 -> B
    int iblk = (t >> 6) & 7;  // i block 0..7
    int dlo  = t & 63;        // d lane 0..63 (k adds 64)

    float acc[4][4];
#pragma unroll
    for (int a = 0; a < 4; a++)
#pragma unroll
        for (int b = 0; b < 4; b++) acc[a][b] = 0.0f;

    for (int ck = 0; ck < DIM; ck += 128) {
        __syncthreads();
        {
            int bX = half ? bj : bi;
            float (*T)[TPAD] = half ? Bt : At;
            const float* src = &d_centers[(bX * 32 + iblk * 4) * DIM + ck];
#pragma unroll
            for (int k = 0; k < 2; k++) {
                int dd = dlo + k * 64;
                float4 v;
                v.x = src[0 * DIM + dd];
                v.y = src[1 * DIM + dd];
                v.z = src[2 * DIM + dd];
                v.w = src[3 * DIM + dd];
                *(float4*)&T[dd][iblk * 4] = v;
            }
        }
        __syncthreads();

        // slice ds covers local rows [ds*8, ds*8+8)
#pragma unroll
        for (int k = 0; k < 8; k++) {
            int dl = ds * 8 + k;
            float4 aV = *(float4*)&At[dl][ti * 4];
            float4 bV = *(float4*)&Bt[dl][tj * 4];
            acc[0][0] += aV.x * bV.x; acc[0][1] += aV.x * bV.y;
            acc[0][2] += aV.x * bV.z; acc[0][3] += aV.x * bV.w;
            acc[1][0] += aV.y * bV.x; acc[1][1] += aV.y * bV.y;
            acc[1][2] += aV.y * bV.z; acc[1][3] += aV.y * bV.w;
            acc[2][0] += aV.z * bV.x; acc[2][1] += aV.z * bV.y;
            acc[2][2] += aV.z * bV.z; acc[2][3] += aV.z * bV.w;
            acc[3][0] += aV.w * bV.x; acc[3][1] += aV.w * bV.y;
            acc[3][2] += aV.w * bV.z; acc[3][3] += aV.w * bV.w;
        }
    }

    // two-wave slice reduction: red[(sl*64+tt)*17 + e], sl = ds mod 8
    __syncthreads();
    float* red = S;           // needs 8*64*17 = 8704 floats <= 9216
    if (ds < 8) {
#pragma unroll
        for (int a = 0; a < 4; a++)
#pragma unroll
            for (int b = 0; b < 4; b++)
                red[((ds)*64 + tt) * 17 + a * 4 + b] = acc[a][b];
    }
    __syncthreads();
    if (ds >= 8) {
#pragma unroll
        for (int a = 0; a < 4; a++)
#pragma unroll
            for (int b = 0; b < 4; b++)
                red[((ds - 8) * 64 + tt) * 17 + a * 4 + b] += acc[a][b];
    }
    __syncthreads();

    // gather: one pair per thread
    float local = 0.0f;
    {
        int pp  = t;              // pair 0..1023
        int tt2 = pp >> 4;
        int e   = pp & 15;
        float dot = 0.0f;
#pragma unroll
        for (int sl = 0; sl < 8; sl++)
            dot += red[(sl * 64 + tt2) * 17 + e];
        int i2 = (tt2 >> 3) * 4 + (e >> 2);
        int j2 = (tt2 & 7) * 4 + (e & 3);
        int gi = bi * 32 + i2;
        int gj = bj * 32 + j2;
        if (gi < gj) {
            float sq = d_norms[gi] + d_norms[gj] - 2.0f * dot;
            local += sqrtf(fmaxf(sq, 1e-12f));
        }
    }

#pragma unroll
    for (int o = 16; o > 0; o >>= 1)
        local += __shfl_down_sync(0xFFFFFFFFu, local, o);
    if ((t & 31) == 0) partw[t >> 5] = local;
    __syncthreads();
    if (t == 0) {
        float sum = 0.0f;
#pragma unroll
        for (int i = 0; i < 32; i++) sum += partw[i];
        atomicAdd(&d_pair_sum, sum);
        __threadfence();
        int prev = atomicAdd(&d_done, 1);
        if (prev == NTILES - 1) {
            __threadfence();
            out[0] = -(*(volatile float*)&d_pair_sum) / (float)NPAIRS;
        }
    }
}

// ---------------------------------------------------------------------------
extern "C" void kernel_launch(void* const* d_in, const int* in_sizes, int n_in,
                              void* d_out, int out_size) {
    const float* matrix = (const float*)d_in[0];
    const int*   label  = (const int*)d_in[1];
    float*       out    = (float*)d_out;

    k_init<<<1, 512>>>();
    k_scatter<<<SCTAS, 512>>>(label);
    k_sums<<<CLUSTER * 2, 256>>>(matrix);
    k_pdist<<<NTILES, 1024>>>(out);
}